// round 1
// baseline (speedup 1.0000x reference)
#include <cuda_runtime.h>

// Problem constants
#define C_DIM   384
#define N_DIM   1152
#define B_SZ    8
#define H_IMG   224
#define W_IMG   224
#define HWB     50176          // H*W per batch
#define M_TOT   401408         // B*H*W tokens
#define HD      96             // head dim
#define NHEADS  4

// QKV scratch in natural token order: [M_TOT][1152]
__device__ float g_qkv[(size_t)M_TOT * N_DIM];

// ---------------------------------------------------------------------------
// Kernel 1: QKV = x^T @ W^T + b, computed directly from NCHW x.
// A (x) is K-major over tokens (stride H*W per channel) -> load [k][m] tiles
// coalesced over m. Each block owns a 64-token strip across ALL N=1152.
// ---------------------------------------------------------------------------
#define BM 64
#define BN 64
#define BK 32
#define AST 68                 // padded stride for As [384][68]
#define BST 68                 // padded stride for Bs [32][68]
#define QKV_SMEM ((C_DIM * AST + BK * BST) * sizeof(float))   // 113,152 B

__global__ void __launch_bounds__(256, 2) qkv_kernel(
    const float* __restrict__ x,
    const float* __restrict__ w,
    const float* __restrict__ bias)
{
    extern __shared__ float sm[];
    float* As = sm;                   // [k][m], k in 0..383, m in 0..63
    float* Bs = sm + C_DIM * AST;     // [kk][n], kk in 0..31, n in 0..63

    const int tid = threadIdx.x;
    const int m0  = blockIdx.x * BM;  // 50176 % 64 == 0 -> never straddles batch
    const int b   = m0 / HWB;
    const int hw0 = m0 - b * HWB;
    const float* xb = x + (size_t)b * C_DIM * HWB + hw0;

    // Load A strip once: coalesced over m, conflict-free STS ((4k+m)%32)
    for (int idx = tid; idx < C_DIM * BM; idx += 256) {
        int k = idx >> 6;
        int m = idx & 63;
        As[k * AST + m] = xb[(size_t)k * HWB + m];
    }

    const int tx = tid & 15;          // m direction (4 rows each)
    const int ty = tid >> 4;          // n direction (4 cols each)
    float* orow = g_qkv + (size_t)m0 * N_DIM;

    for (int n0 = 0; n0 < N_DIM; n0 += BN) {
        float acc[4][4];
        #pragma unroll
        for (int j = 0; j < 4; j++) {
            float bv = bias[n0 + ty * 4 + j];
            #pragma unroll
            for (int i = 0; i < 4; i++) acc[i][j] = bv;
        }

        for (int k0 = 0; k0 < C_DIM; k0 += BK) {
            __syncthreads();   // covers initial As load + previous Bs readers
            #pragma unroll
            for (int idx = tid; idx < BN * BK; idx += 256) {
                int n  = idx >> 5;
                int kk = idx & 31;
                Bs[kk * BST + n] = w[(size_t)(n0 + n) * C_DIM + k0 + kk];
            }
            __syncthreads();

            #pragma unroll
            for (int kk = 0; kk < BK; kk++) {
                float4 a  = *(const float4*)(As + (k0 + kk) * AST + tx * 4);
                float4 bb = *(const float4*)(Bs + kk * BST + ty * 4);
                acc[0][0] += a.x * bb.x; acc[0][1] += a.x * bb.y;
                acc[0][2] += a.x * bb.z; acc[0][3] += a.x * bb.w;
                acc[1][0] += a.y * bb.x; acc[1][1] += a.y * bb.y;
                acc[1][2] += a.y * bb.z; acc[1][3] += a.y * bb.w;
                acc[2][0] += a.z * bb.x; acc[2][1] += a.z * bb.y;
                acc[2][2] += a.z * bb.z; acc[2][3] += a.z * bb.w;
                acc[3][0] += a.w * bb.x; acc[3][1] += a.w * bb.y;
                acc[3][2] += a.w * bb.z; acc[3][3] += a.w * bb.w;
            }
        }

        // Store: ty pairs form contiguous 32B sectors per row
        #pragma unroll
        for (int i = 0; i < 4; i++) {
            float4 v = make_float4(acc[i][0], acc[i][1], acc[i][2], acc[i][3]);
            *(float4*)(orow + (size_t)(tx * 4 + i) * N_DIM + n0 + ty * 4) = v;
        }
    }
}

// ---------------------------------------------------------------------------
// Kernel 2: windowed attention, one block per (window, head).
// q,k stored [d][p] (transposed) so score compute is float4-over-p;
// scores stored [j][i] so both softmax and the AV GEMM read it cleanly;
// v stored [p][d]; output staged in SMEM then written w-contiguously.
// ---------------------------------------------------------------------------
#define SD   52      // [d][p] stride (p padded 49 -> 52)
#define VST  100     // [p][d] stride
#define SCST 52      // sc [j][i] stride
#define ATTN_SMEM ((2 * 96 * SD + 52 * VST + 52 * SCST) * sizeof(float))  // 71,552 B

__global__ void __launch_bounds__(256) attn_kernel(float* __restrict__ out)
{
    extern __shared__ float sm[];
    float* qs = sm;                   // [96][52]  (q * scale, [d][p])
    float* ks = qs + 96 * SD;         // [96][52]  ([d][p])
    float* vs = ks + 96 * SD;         // [52][100] ([p][d])
    float* sc = vs + 52 * VST;        // [52][52]  (scores [j][i], later attn)

    const int tid  = threadIdx.x;
    const int win  = blockIdx.x;
    const int head = blockIdx.y;
    const int b    = win >> 10;
    const int wh   = (win >> 5) & 31;
    const int ww   = win & 31;
    const float scale = 0.10206207261596577f;  // 96^-0.5

    // Zero the pad columns p=49..51 of qs/ks (score tiles read up to p=51)
    for (int e = tid; e < 3 * 96; e += 256) {
        int d = e % 96;
        int p = 49 + e / 96;
        qs[d * SD + p] = 0.f;
        ks[d * SD + p] = 0.f;
    }

    // Load q,k,v: coalesced over d (96 floats contiguous per token)
    for (int e = tid; e < 49 * 96; e += 256) {
        int d = e % 96;
        int p = e / 96;
        int ph = p / 7;
        int h  = wh * 7 + ph;
        int wc = ww * 7 + (p - ph * 7);
        const float* row = g_qkv + ((size_t)b * HWB + h * W_IMG + wc) * N_DIM + head * HD;
        qs[d * SD + p] = row[d] * scale;
        ks[d * SD + p] = row[C_DIM + d];
        vs[p * VST + d] = row[2 * C_DIM + d];
    }
    __syncthreads();

    // Scores: 13x13 tiles of 4x4 -> sc[j][i] = q_i . k_j
    if (tid < 169) {
        const int ti = (tid % 13) * 4;
        const int tj = (tid / 13) * 4;
        float acc[4][4] = {};          // [ii][jj]
        for (int d = 0; d < 96; d++) {
            float4 qv = *(const float4*)(qs + d * SD + ti);
            float4 kv = *(const float4*)(ks + d * SD + tj);
            acc[0][0] += qv.x * kv.x; acc[0][1] += qv.x * kv.y;
            acc[0][2] += qv.x * kv.z; acc[0][3] += qv.x * kv.w;
            acc[1][0] += qv.y * kv.x; acc[1][1] += qv.y * kv.y;
            acc[1][2] += qv.y * kv.z; acc[1][3] += qv.y * kv.w;
            acc[2][0] += qv.z * kv.x; acc[2][1] += qv.z * kv.y;
            acc[2][2] += qv.z * kv.z; acc[2][3] += qv.z * kv.w;
            acc[3][0] += qv.w * kv.x; acc[3][1] += qv.w * kv.y;
            acc[3][2] += qv.w * kv.z; acc[3][3] += qv.w * kv.w;
        }
        #pragma unroll
        for (int jj = 0; jj < 4; jj++) {
            float4 v = make_float4(acc[0][jj], acc[1][jj], acc[2][jj], acc[3][jj]);
            *(float4*)(sc + (tj + jj) * SCST + ti) = v;
        }
    }
    __syncthreads();

    // Softmax over j for each valid row i (reads column i of sc[j][i])
    if (tid < 49) {
        float mx = -1e30f;
        for (int j = 0; j < 49; j++) mx = fmaxf(mx, sc[j * SCST + tid]);
        float sum = 0.f;
        for (int j = 0; j < 49; j++) {
            float ev = __expf(sc[j * SCST + tid] - mx);
            sc[j * SCST + tid] = ev;
            sum += ev;
        }
        float inv = 1.f / sum;
        for (int j = 0; j < 49; j++) sc[j * SCST + tid] *= inv;
    }
    __syncthreads();

    // out[p][d] = sum_j attn[p][j] * v[j][d];  attn[p][j] == sc[j][p]
    // 13 p-tiles x 24 d-tiles = 312 tiles of 4x4. Stage into osm (reuses qs).
    float* osm = qs;   // needs 49*100 = 4900 <= 96*52 = 4992 floats
    for (int tile = tid; tile < 312; tile += 256) {
        int p0 = (tile % 13) * 4;
        int d0 = (tile / 13) * 4;
        float acc[4][4] = {};          // [pp][dd]
        for (int j = 0; j < 49; j++) {
            float4 av = *(const float4*)(sc + j * SCST + p0);
            float4 vv = *(const float4*)(vs + j * VST + d0);
            acc[0][0] += av.x * vv.x; acc[0][1] += av.x * vv.y;
            acc[0][2] += av.x * vv.z; acc[0][3] += av.x * vv.w;
            acc[1][0] += av.y * vv.x; acc[1][1] += av.y * vv.y;
            acc[1][2] += av.y * vv.z; acc[1][3] += av.y * vv.w;
            acc[2][0] += av.z * vv.x; acc[2][1] += av.z * vv.y;
            acc[2][2] += av.z * vv.z; acc[2][3] += av.z * vv.w;
            acc[3][0] += av.w * vv.x; acc[3][1] += av.w * vv.y;
            acc[3][2] += av.w * vv.z; acc[3][3] += av.w * vv.w;
        }
        #pragma unroll
        for (int pp = 0; pp < 4; pp++) {
            if (p0 + pp < 49) {
                float4 o4 = make_float4(acc[pp][0], acc[pp][1], acc[pp][2], acc[pp][3]);
                *(float4*)(osm + (p0 + pp) * VST + d0) = o4;
            }
        }
    }
    __syncthreads();

    // Coalesced-ish write: consecutive threads -> consecutive w within a row
    for (int e = tid; e < 49 * 96; e += 256) {
        int p = e % 49;
        int d = e / 49;
        int ph = p / 7;
        int h  = wh * 7 + ph;
        int wc = ww * 7 + (p - ph * 7);
        out[(((size_t)b * C_DIM + head * HD + d) * H_IMG + h) * W_IMG + wc] =
            osm[p * VST + d];
    }
}

// ---------------------------------------------------------------------------
extern "C" void kernel_launch(void* const* d_in, const int* in_sizes, int n_in,
                              void* d_out, int out_size)
{
    const float* x    = (const float*)d_in[0];
    const float* w    = (const float*)d_in[1];
    const float* bias = (const float*)d_in[2];
    float* out        = (float*)d_out;

    // Idempotent host-side attribute sets (not stream ops; capture-safe)
    cudaFuncSetAttribute(qkv_kernel, cudaFuncAttributeMaxDynamicSharedMemorySize,
                         (int)QKV_SMEM);
    cudaFuncSetAttribute(attn_kernel, cudaFuncAttributeMaxDynamicSharedMemorySize,
                         (int)ATTN_SMEM);

    qkv_kernel<<<M_TOT / BM, 256, QKV_SMEM>>>(x, w, bias);
    attn_kernel<<<dim3(B_SZ * 32 * 32, NHEADS), 256, ATTN_SMEM>>>(out);
}

// round 3
// speedup vs baseline: 1.9136x; 1.9136x over previous
#include <cuda_runtime.h>
#include <cstdint>

// Problem constants
#define C_DIM   384
#define N_DIM   1152
#define B_SZ    8
#define H_IMG   224
#define W_IMG   224
#define HWB     50176
#define M_TOT   401408
#define HD      96
#define NHEADS  4

// QKV scratch in natural token order: [M_TOT][1152]
__device__ float g_qkv[(size_t)M_TOT * N_DIM];

__device__ __forceinline__ uint32_t f2tf(float f) {
    uint32_t r; asm("cvt.rna.tf32.f32 %0, %1;" : "=r"(r) : "f"(f)); return r;
}

__device__ __forceinline__ void mma_tf32(float& c0, float& c1, float& c2, float& c3,
                                         uint32_t a0, uint32_t a1, uint32_t a2, uint32_t a3,
                                         uint32_t b0, uint32_t b1) {
    asm volatile(
        "mma.sync.aligned.m16n8k8.row.col.f32.tf32.tf32.f32 "
        "{%0,%1,%2,%3}, {%4,%5,%6,%7}, {%8,%9}, {%0,%1,%2,%3};"
        : "+f"(c0), "+f"(c1), "+f"(c2), "+f"(c3)
        : "r"(a0), "r"(a1), "r"(a2), "r"(a3), "r"(b0), "r"(b1));
}

// ---------------------------------------------------------------------------
// Kernel 1: QKV GEMM with tf32 mma.sync (sm_80-class, legal on compute_103).
//   C[m=128 tokens][n=1152 ch] = A[m][k=384] * W^T, A resident, N swept.
//   As[k][m] / Bs[k][n], stride 136 -> conflict-free fragment LDS.
// ---------------------------------------------------------------------------
#define AST 136
#define QKV_SMEM ((384 * AST + 32 * AST) * 4)     // 226,304 B

__global__ void __launch_bounds__(256, 1) qkv_mma(
    const float* __restrict__ x,
    const float* __restrict__ w,
    const float* __restrict__ bias)
{
    extern __shared__ uint32_t smu[];
    uint32_t* As = smu;                 // [384][136] tf32, [k][m]
    uint32_t* Bs = smu + 384 * AST;     // [32][136]  tf32, [k][n]

    const int tid = threadIdx.x;
    const int wid = tid >> 5;
    const int lid = tid & 31;
    const int mw  = wid & 1;            // 2 m-subtiles of 64
    const int nw  = wid >> 1;           // 4 n-subtiles of 32

    const int m0 = blockIdx.x * 128;    // 50176 % 128 == 0
    const int b  = m0 / HWB;
    const float* xb = x + (size_t)b * C_DIM * HWB + (m0 - b * HWB);

    // ---- Load A once: 384 k-rows x 128 tokens, coalesced over m ----
    for (int i = tid; i < 12288; i += 256) {          // 12288 float4
        int k = i >> 5, m4 = i & 31;
        float4 v = *(const float4*)(xb + (size_t)k * HWB + m4 * 4);
        uint32_t* d = As + k * AST + m4 * 4;
        d[0] = f2tf(v.x); d[1] = f2tf(v.y); d[2] = f2tf(v.z); d[3] = f2tf(v.w);
    }

    const int lq = lid >> 2;            // 0..7
    const int lr = lid & 3;             // 0..3

    for (int nt = 0; nt < 9; ++nt) {
        const int n0 = nt * 128;
        float c[4][4][4];               // [m-tile][n-tile][frag]
        #pragma unroll
        for (int i = 0; i < 4; ++i)
            #pragma unroll
            for (int j = 0; j < 4; ++j)
                c[i][j][0] = c[i][j][1] = c[i][j][2] = c[i][j][3] = 0.f;

        for (int ks = 0; ks < 12; ++ks) {
            __syncthreads();            // prior-stage readers done
            // Load B stage: W[n0+n][ks*32 .. +32) -> Bs[k][n]
            const float* wp = w + (size_t)n0 * C_DIM + ks * 32;
            #pragma unroll
            for (int p = 0; p < 4; ++p) {
                int idx = p * 256 + tid;
                int n = idx & 127, kq = idx >> 7;     // kq: 0..7 (4 k each)
                float4 v = *(const float4*)(wp + (size_t)n * C_DIM + kq * 4);
                Bs[(kq * 4 + 0) * AST + n] = f2tf(v.x);
                Bs[(kq * 4 + 1) * AST + n] = f2tf(v.y);
                Bs[(kq * 4 + 2) * AST + n] = f2tf(v.z);
                Bs[(kq * 4 + 3) * AST + n] = f2tf(v.w);
            }
            __syncthreads();

            #pragma unroll
            for (int kc = 0; kc < 4; ++kc) {
                const int kkA = ks * 32 + kc * 8 + lr;    // global k for A
                const int kkB = kc * 8 + lr;              // stage-local k for B
                uint32_t a[4][4], bb[4][2];
                #pragma unroll
                for (int i = 0; i < 4; ++i) {
                    int r = mw * 64 + i * 16 + lq;
                    a[i][0] = As[kkA * AST + r];
                    a[i][1] = As[kkA * AST + r + 8];
                    a[i][2] = As[(kkA + 4) * AST + r];
                    a[i][3] = As[(kkA + 4) * AST + r + 8];
                }
                #pragma unroll
                for (int j = 0; j < 4; ++j) {
                    int n = nw * 32 + j * 8 + lq;
                    bb[j][0] = Bs[kkB * AST + n];
                    bb[j][1] = Bs[(kkB + 4) * AST + n];
                }
                #pragma unroll
                for (int i = 0; i < 4; ++i)
                    #pragma unroll
                    for (int j = 0; j < 4; ++j)
                        mma_tf32(c[i][j][0], c[i][j][1], c[i][j][2], c[i][j][3],
                                 a[i][0], a[i][1], a[i][2], a[i][3],
                                 bb[j][0], bb[j][1]);
            }
        }

        // ---- Epilogue: bias + float2 stores ----
        #pragma unroll
        for (int j = 0; j < 4; ++j) {
            const int gn = n0 + nw * 32 + j * 8 + lr * 2;
            float2 bv = *(const float2*)(bias + gn);
            #pragma unroll
            for (int i = 0; i < 4; ++i) {
                const int gm0 = m0 + mw * 64 + i * 16 + lq;
                float2 v0 = make_float2(c[i][j][0] + bv.x, c[i][j][1] + bv.y);
                float2 v1 = make_float2(c[i][j][2] + bv.x, c[i][j][3] + bv.y);
                *(float2*)(g_qkv + (size_t)gm0 * N_DIM + gn)       = v0;
                *(float2*)(g_qkv + (size_t)(gm0 + 8) * N_DIM + gn) = v1;
            }
        }
    }
}

// ---------------------------------------------------------------------------
// Kernel 2: windowed attention (unchanged from Round 1)
// ---------------------------------------------------------------------------
#define SD   52
#define VST  100
#define SCST 52
#define ATTN_SMEM ((2 * 96 * SD + 52 * VST + 52 * SCST) * sizeof(float))

__global__ void __launch_bounds__(256) attn_kernel(float* __restrict__ out)
{
    extern __shared__ float sm[];
    float* qs = sm;
    float* ks = qs + 96 * SD;
    float* vs = ks + 96 * SD;
    float* sc = vs + 52 * VST;

    const int tid  = threadIdx.x;
    const int win  = blockIdx.x;
    const int head = blockIdx.y;
    const int b    = win >> 10;
    const int wh   = (win >> 5) & 31;
    const int ww   = win & 31;
    const float scale = 0.10206207261596577f;

    for (int e = tid; e < 3 * 96; e += 256) {
        int d = e % 96;
        int p = 49 + e / 96;
        qs[d * SD + p] = 0.f;
        ks[d * SD + p] = 0.f;
    }

    for (int e = tid; e < 49 * 96; e += 256) {
        int d = e % 96;
        int p = e / 96;
        int ph = p / 7;
        int h  = wh * 7 + ph;
        int wc = ww * 7 + (p - ph * 7);
        const float* row = g_qkv + ((size_t)b * HWB + h * W_IMG + wc) * N_DIM + head * HD;
        qs[d * SD + p] = row[d] * scale;
        ks[d * SD + p] = row[C_DIM + d];
        vs[p * VST + d] = row[2 * C_DIM + d];
    }
    __syncthreads();

    if (tid < 169) {
        const int ti = (tid % 13) * 4;
        const int tj = (tid / 13) * 4;
        float acc[4][4] = {};
        for (int d = 0; d < 96; d++) {
            float4 qv = *(const float4*)(qs + d * SD + ti);
            float4 kv = *(const float4*)(ks + d * SD + tj);
            acc[0][0] += qv.x * kv.x; acc[0][1] += qv.x * kv.y;
            acc[0][2] += qv.x * kv.z; acc[0][3] += qv.x * kv.w;
            acc[1][0] += qv.y * kv.x; acc[1][1] += qv.y * kv.y;
            acc[1][2] += qv.y * kv.z; acc[1][3] += qv.y * kv.w;
            acc[2][0] += qv.z * kv.x; acc[2][1] += qv.z * kv.y;
            acc[2][2] += qv.z * kv.z; acc[2][3] += qv.z * kv.w;
            acc[3][0] += qv.w * kv.x; acc[3][1] += qv.w * kv.y;
            acc[3][2] += qv.w * kv.z; acc[3][3] += qv.w * kv.w;
        }
        #pragma unroll
        for (int jj = 0; jj < 4; jj++) {
            float4 v = make_float4(acc[0][jj], acc[1][jj], acc[2][jj], acc[3][jj]);
            *(float4*)(sc + (tj + jj) * SCST + ti) = v;
        }
    }
    __syncthreads();

    if (tid < 49) {
        float mx = -1e30f;
        for (int j = 0; j < 49; j++) mx = fmaxf(mx, sc[j * SCST + tid]);
        float sum = 0.f;
        for (int j = 0; j < 49; j++) {
            float ev = __expf(sc[j * SCST + tid] - mx);
            sc[j * SCST + tid] = ev;
            sum += ev;
        }
        float inv = 1.f / sum;
        for (int j = 0; j < 49; j++) sc[j * SCST + tid] *= inv;
    }
    __syncthreads();

    float* osm = qs;
    for (int tile = tid; tile < 312; tile += 256) {
        int p0 = (tile % 13) * 4;
        int d0 = (tile / 13) * 4;
        float acc[4][4] = {};
        for (int j = 0; j < 49; j++) {
            float4 av = *(const float4*)(sc + j * SCST + p0);
            float4 vv = *(const float4*)(vs + j * VST + d0);
            acc[0][0] += av.x * vv.x; acc[0][1] += av.x * vv.y;
            acc[0][2] += av.x * vv.z; acc[0][3] += av.x * vv.w;
            acc[1][0] += av.y * vv.x; acc[1][1] += av.y * vv.y;
            acc[1][2] += av.y * vv.z; acc[1][3] += av.y * vv.w;
            acc[2][0] += av.z * vv.x; acc[2][1] += av.z * vv.y;
            acc[2][2] += av.z * vv.z; acc[2][3] += av.z * vv.w;
            acc[3][0] += av.w * vv.x; acc[3][1] += av.w * vv.y;
            acc[3][2] += av.w * vv.z; acc[3][3] += av.w * vv.w;
        }
        #pragma unroll
        for (int pp = 0; pp < 4; pp++) {
            if (p0 + pp < 49) {
                float4 o4 = make_float4(acc[pp][0], acc[pp][1], acc[pp][2], acc[pp][3]);
                *(float4*)(osm + (p0 + pp) * VST + d0) = o4;
            }
        }
    }
    __syncthreads();

    for (int e = tid; e < 49 * 96; e += 256) {
        int p = e % 49;
        int d = e / 49;
        int ph = p / 7;
        int h  = wh * 7 + ph;
        int wc = ww * 7 + (p - ph * 7);
        out[(((size_t)b * C_DIM + head * HD + d) * H_IMG + h) * W_IMG + wc] =
            osm[p * VST + d];
    }
}

// ---------------------------------------------------------------------------
extern "C" void kernel_launch(void* const* d_in, const int* in_sizes, int n_in,
                              void* d_out, int out_size)
{
    const float* x    = (const float*)d_in[0];
    const float* w    = (const float*)d_in[1];
    const float* bias = (const float*)d_in[2];
    float* out        = (float*)d_out;

    cudaFuncSetAttribute(qkv_mma, cudaFuncAttributeMaxDynamicSharedMemorySize,
                         (int)QKV_SMEM);
    cudaFuncSetAttribute(attn_kernel, cudaFuncAttributeMaxDynamicSharedMemorySize,
                         (int)ATTN_SMEM);

    qkv_mma<<<M_TOT / 128, 256, QKV_SMEM>>>(x, w, bias);
    attn_kernel<<<dim3(B_SZ * 32 * 32, NHEADS), 256, ATTN_SMEM>>>(out);
}